// round 8
// baseline (speedup 1.0000x reference)
#include <cuda_runtime.h>
#include <cuda_fp16.h>
#include <stdint.h>
#include <math.h>

// ----------------------------------------------------------------------------
// UPTRec forward. Round 8 (= round 7 with the pair-shfl mask fixed):
// attention 512 thr / 2 thr per query, 3-stage cp.async GEMMs.
// ----------------------------------------------------------------------------

constexpr int Bn   = 512;
constexpr int Tn   = 256;
constexpr int Cn   = 256;
constexpr int Hn   = 4;
constexpr int DHn  = 64;
constexpr int Ln   = 2;
constexpr int Kcl  = 16;
constexpr int ITEM_H = 192;
constexpr int USER_H = 64;
constexpr int NTOK = Bn * Tn;          // 131072
constexpr int NC   = NTOK * Cn;        // 33,554,432

// fp32 scratch
__device__ float g_x[NC];
__device__ float g_qin[NC];
__device__ int   g_ids[NTOK];
// fp16 buffers
__device__ __align__(16) __half g_xh[NC];
__device__ __align__(16) __half g_qinh[NC];
__device__ __align__(16) __half g_attnh[NC];
__device__ __align__(16) __half g_h1h[NC];
__device__ __align__(16) __half g_Qh[NC];
__device__ __align__(16) __half g_Kh[NC];
__device__ __align__(16) __half g_Vh[NC];
// fp16 weights: [4 arrays][L][C][C] order q,o,W1,W2
__device__ __align__(16) __half g_Wh[4 * Ln * Cn * Cn];
// fused KV weights: [L][C][2C]  (cols 0..255 = Wk, 256..511 = Wv)
__device__ __align__(16) __half g_Wkvh[Ln * Cn * 2 * Cn];

// ----------------------------------------------------------------------------
__device__ __forceinline__ float warp_sum(float v) {
    v += __shfl_xor_sync(0xffffffffu, v, 16);
    v += __shfl_xor_sync(0xffffffffu, v, 8);
    v += __shfl_xor_sync(0xffffffffu, v, 4);
    v += __shfl_xor_sync(0xffffffffu, v, 2);
    v += __shfl_xor_sync(0xffffffffu, v, 1);
    return v;
}

__device__ __forceinline__ void cp_async16(uint32_t saddr, const void* gptr) {
    asm volatile("cp.async.cg.shared.global [%0], [%1], 16;\n" :: "r"(saddr), "l"(gptr));
}
__device__ __forceinline__ void cp_commit() {
    asm volatile("cp.async.commit_group;\n");
}
template <int N>
__device__ __forceinline__ void cp_wait() {
    asm volatile("cp.async.wait_group %0;\n" :: "n"(N));
}

// ----------------------------------------------------------------------------
// Embedding (unmasked x for k-means)
// ----------------------------------------------------------------------------
__global__ void embed_kernel(const int* __restrict__ uid,
                             const int* __restrict__ seq,
                             const float* __restrict__ item_emb,
                             const float* __restrict__ user_emb,
                             const float* __restrict__ pos_emb) {
    int idx = blockIdx.x * blockDim.x + threadIdx.x;
    if (idx >= NC) return;
    int i = idx >> 8;
    int c = idx & 255;
    int b = i >> 8;
    int t = i & 255;
    float v;
    if (c < ITEM_H) v = item_emb[seq[i] * ITEM_H + c];
    else            v = user_emb[uid[b] * USER_H + (c - ITEM_H)];
    g_x[idx] = v + pos_emb[t * Cn + c];
}

// merged fp32 -> fp16 weight conversion: q,o,W1,W2 then fused KV
__global__ void convall_kernel(const float* __restrict__ Wq, const float* __restrict__ Wo,
                               const float* __restrict__ W1, const float* __restrict__ W2,
                               const float* __restrict__ Wk, const float* __restrict__ Wv) {
    int idx = blockIdx.x * blockDim.x + threadIdx.x;
    const int per = Ln * Cn * Cn;            // 131072
    if (idx < 4 * per) {
        int a = idx / per;
        int r = idx - a * per;
        const float* s;
        switch (a) {
            case 0: s = Wq; break; case 1: s = Wo; break;
            case 2: s = W1; break; default: s = W2; break;
        }
        g_Wh[idx] = __float2half(s[r]);
        return;
    }
    int j = idx - 4 * per;
    if (j >= Ln * Cn * 2 * Cn) return;
    int l = j / (Cn * 2 * Cn);
    int r = j - l * (Cn * 2 * Cn);
    int k = r / (2 * Cn);
    int n = r - k * (2 * Cn);
    float v = (n < Cn) ? Wk[(l * Cn + k) * Cn + n] : Wv[(l * Cn + k) * Cn + (n - Cn)];
    g_Wkvh[j] = __float2half(v);
}

// ----------------------------------------------------------------------------
// Batched Lloyd k-means (exact fp32) + fused pad-mask epilogue
// ----------------------------------------------------------------------------
__global__ __launch_bounds__(256) void kmeans_kernel(const int* __restrict__ seq) {
    __shared__ float cent[Kcl * Cn];
    __shared__ float xsq[Tn];
    __shared__ float csq[Kcl];
    __shared__ int   sids[Tn];
    __shared__ int   cnt[Kcl];

    const int b    = blockIdx.x;
    const int tid  = threadIdx.x;
    const int lane = tid & 31;
    const int warp = tid >> 5;
    float* Xb = g_x + b * Tn * Cn;

    for (int i = tid; i < Kcl * Cn; i += 256) cent[i] = Xb[i];

    for (int r = 0; r < 32; r++) {
        int t = warp * 32 + r;
        float s = 0.f;
        #pragma unroll
        for (int j = 0; j < 8; j++) {
            float xv = Xb[t * Cn + lane + 32 * j];
            s += xv * xv;
        }
        s = warp_sum(s);
        if (lane == 0) xsq[t] = s;
    }
    __syncthreads();

    for (int iter = 0; iter <= 10; iter++) {
        if (tid < Kcl) {
            float s = 0.f;
            for (int c = 0; c < Cn; c++) { float v = cent[tid * Cn + c]; s += v * v; }
            csq[tid] = s;
        }
        __syncthreads();

        for (int r = 0; r < 32; r++) {
            int t = warp * 32 + r;
            float xv[8];
            #pragma unroll
            for (int j = 0; j < 8; j++) xv[j] = Xb[t * Cn + lane + 32 * j];
            float best = 3.4e38f; int bi = 0;
            #pragma unroll
            for (int k = 0; k < Kcl; k++) {
                float p = 0.f;
                #pragma unroll
                for (int j = 0; j < 8; j++) p += xv[j] * cent[k * Cn + lane + 32 * j];
                p = warp_sum(p);
                float d = xsq[t] - 2.0f * p + csq[k];
                if (d < best) { best = d; bi = k; }
            }
            if (lane == 0) sids[t] = bi;
        }
        __syncthreads();

        if (iter == 10) break;

        if (tid < Kcl) cnt[tid] = 0;
        __syncthreads();
        atomicAdd(&cnt[sids[tid]], 1);
        __syncthreads();

        {
            const int c = tid;
            float acc[Kcl];
            #pragma unroll
            for (int k = 0; k < Kcl; k++) acc[k] = 0.f;
            for (int t = 0; t < Tn; t++) {
                float v = Xb[t * Cn + c];
                int id = sids[t];
                #pragma unroll
                for (int k = 0; k < Kcl; k++) acc[k] += (id == k) ? v : 0.f;
            }
            __syncthreads();
            #pragma unroll
            for (int k = 0; k < Kcl; k++) {
                if (cnt[k] > 0) cent[k * Cn + c] = acc[k] / fmaxf((float)cnt[k], 1.0f);
            }
        }
        __syncthreads();
    }

    g_ids[b * Tn + tid] = sids[tid];

    // fused pad-mask + fp16 mirror
    __syncthreads();
    __half* Xh = g_xh + b * Tn * Cn;
    for (int idx = tid; idx < Tn * Cn; idx += 256) {
        int t = idx >> 8;
        float v = Xb[idx];
        if (seq[b * Tn + t] == 0) v = 0.0f;
        Xb[idx] = v;
        Xh[idx] = __float2half(v);
    }
}

// ----------------------------------------------------------------------------
// LayerNorm: warp per row; WF32 controls fp32 store
// ----------------------------------------------------------------------------
template <bool WF32>
__global__ __launch_bounds__(256) void ln_kernel(const float* __restrict__ in,
                                                 float* __restrict__ out,
                                                 __half* __restrict__ outh,
                                                 const float* __restrict__ g,
                                                 const float* __restrict__ bb) {
    int lane = threadIdx.x & 31, warp = threadIdx.x >> 5;
    int row = blockIdx.x * 8 + warp;
    const float* r = in + row * Cn;
    float v[8];
    #pragma unroll
    for (int j = 0; j < 8; j++) v[j] = r[lane + 32 * j];
    float s = 0.f;
    #pragma unroll
    for (int j = 0; j < 8; j++) s += v[j];
    s = warp_sum(s);
    float mu = s * (1.0f / 256.0f);
    float q = 0.f;
    #pragma unroll
    for (int j = 0; j < 8; j++) { float d = v[j] - mu; q += d * d; }
    q = warp_sum(q);
    float rinv = rsqrtf(q * (1.0f / 256.0f) + 1e-8f);
    #pragma unroll
    for (int j = 0; j < 8; j++) {
        int c = lane + 32 * j;
        float o = g[c] * (v[j] - mu) * rinv + bb[c];
        if (WF32) out[row * Cn + c] = o;
        outh[row * Cn + c] = __float2half(o);
    }
}

// ----------------------------------------------------------------------------
// fp16 tensor-core GEMM, 3-stage cp.async pipeline.
// MODE 0: half out = acc
// MODE 1: fp32 out = (acc + res) * keep
// MODE 2: half out = relu(acc + bias)
// MODE 3: fp32+half out = (acc+bias+res)*keep
// MODE 4: half out routed K/V halves, NSTR=512
// ----------------------------------------------------------------------------
__device__ __forceinline__ void ldsm4(uint32_t* r, uint32_t addr) {
    asm volatile("ldmatrix.sync.aligned.m8n8.x4.shared.b16 {%0,%1,%2,%3}, [%4];"
        : "=r"(r[0]), "=r"(r[1]), "=r"(r[2]), "=r"(r[3]) : "r"(addr));
}
__device__ __forceinline__ void ldsm4t(uint32_t* r, uint32_t addr) {
    asm volatile("ldmatrix.sync.aligned.m8n8.x4.trans.shared.b16 {%0,%1,%2,%3}, [%4];"
        : "=r"(r[0]), "=r"(r[1]), "=r"(r[2]), "=r"(r[3]) : "r"(addr));
}
__device__ __forceinline__ void mma16816(float* c, const uint32_t* a, const uint32_t* b) {
    asm volatile("mma.sync.aligned.m16n8k16.row.col.f32.f16.f16.f32 "
        "{%0,%1,%2,%3}, {%4,%5,%6,%7}, {%8,%9}, {%0,%1,%2,%3};"
        : "+f"(c[0]), "+f"(c[1]), "+f"(c[2]), "+f"(c[3])
        : "r"(a[0]), "r"(a[1]), "r"(a[2]), "r"(a[3]), "r"(b[0]), "r"(b[1]));
}

constexpr int BKg   = 32;
constexpr int AROW  = BKg + 8;
constexpr int BROW  = 128 + 8;
constexpr int ASTG  = 128 * AROW;
constexpr int BSTG  = BKg * BROW;
constexpr int GEMM_SMEM = (3 * (ASTG + BSTG)) * 2;   // 56832 bytes

template <int MODE, int NSTR>
__global__ __launch_bounds__(256, 2) void hgemm_kernel(const __half* __restrict__ A,
                                                       const __half* __restrict__ W,
                                                       float* __restrict__ Cout,
                                                       __half* __restrict__ CoutH,
                                                       const float* __restrict__ res,
                                                       const float* __restrict__ bias,
                                                       const int* __restrict__ seq) {
    extern __shared__ __align__(16) __half dsm[];
    __half* Asm = dsm;
    __half* Bsm = dsm + 3 * ASTG;

    const int tid  = threadIdx.x;
    const int lane = tid & 31;
    const int warp = tid >> 5;
    const int wm   = warp >> 2;
    const int wn   = warp & 3;
    const int m0   = blockIdx.y * 128;
    const int n0   = blockIdx.x * 128;

    float acc[4][4][4];
    #pragma unroll
    for (int i = 0; i < 4; i++)
        #pragma unroll
        for (int j = 0; j < 4; j++)
            #pragma unroll
            for (int v = 0; v < 4; v++) acc[i][j][v] = 0.f;

    const int a_row0 = tid >> 2,          a_c0 = (tid & 3) * 8;
    const int a_row1 = (tid + 256) >> 2,  a_c1 = ((tid + 256) & 3) * 8;
    const int b_row0 = tid >> 4,          b_c0 = (tid & 15) * 8;
    const int b_row1 = (tid + 256) >> 4,  b_c1 = ((tid + 256) & 15) * 8;

    auto load_stage = [&](int s, int k0) {
        __half* As = Asm + s * ASTG;
        __half* Bs = Bsm + s * BSTG;
        cp_async16((uint32_t)__cvta_generic_to_shared(As + a_row0 * AROW + a_c0),
                   A + (m0 + a_row0) * 256 + k0 + a_c0);
        cp_async16((uint32_t)__cvta_generic_to_shared(As + a_row1 * AROW + a_c1),
                   A + (m0 + a_row1) * 256 + k0 + a_c1);
        cp_async16((uint32_t)__cvta_generic_to_shared(Bs + b_row0 * BROW + b_c0),
                   W + (k0 + b_row0) * NSTR + n0 + b_c0);
        cp_async16((uint32_t)__cvta_generic_to_shared(Bs + b_row1 * BROW + b_c1),
                   W + (k0 + b_row1) * NSTR + n0 + b_c1);
        cp_commit();
    };

    load_stage(0, 0);
    load_stage(1, BKg);

    for (int it = 0; it < 8; it++) {
        const int s = it % 3;
        if (it < 6) cp_wait<1>(); else cp_wait<0>();
        __syncthreads();
        if (it < 6) load_stage((it + 2) % 3, (it + 2) * BKg);

        uint32_t as_base = (uint32_t)__cvta_generic_to_shared(Asm + s * ASTG);
        uint32_t bs_base = (uint32_t)__cvta_generic_to_shared(Bsm + s * BSTG);

        #pragma unroll
        for (int kk = 0; kk < BKg; kk += 16) {
            uint32_t aF[4][4];
            uint32_t bF[4][2];
            #pragma unroll
            for (int mt = 0; mt < 4; mt++) {
                int row = wm * 64 + mt * 16 + (lane & 15);
                int col = kk + (lane >> 4) * 8;
                ldsm4(aF[mt], as_base + (uint32_t)((row * AROW + col) * 2));
            }
            #pragma unroll
            for (int np = 0; np < 2; np++) {
                int k = kk + (lane & 15);
                int n = wn * 32 + np * 16 + (lane >> 4) * 8;
                uint32_t r[4];
                ldsm4t(r, bs_base + (uint32_t)((k * BROW + n) * 2));
                bF[np * 2][0] = r[0]; bF[np * 2][1] = r[1];
                bF[np * 2 + 1][0] = r[2]; bF[np * 2 + 1][1] = r[3];
            }
            #pragma unroll
            for (int mt = 0; mt < 4; mt++)
                #pragma unroll
                for (int nt = 0; nt < 4; nt++)
                    mma16816(acc[mt][nt], aF[mt], bF[nt]);
        }
    }

    const int gid = lane >> 2, tig = lane & 3;
    #pragma unroll
    for (int mt = 0; mt < 4; mt++) {
        #pragma unroll
        for (int hr = 0; hr < 2; hr++) {
            int m = m0 + wm * 64 + mt * 16 + gid + hr * 8;
            float keep = 1.0f;
            if (MODE == 1 || MODE == 3) keep = (seq[m] != 0) ? 1.0f : 0.0f;
            #pragma unroll
            for (int nt = 0; nt < 4; nt++) {
                int n = n0 + wn * 32 + nt * 8 + tig * 2;
                float v0 = acc[mt][nt][hr * 2 + 0];
                float v1 = acc[mt][nt][hr * 2 + 1];
                if (MODE == 2 || MODE == 3) { v0 += bias[n]; v1 += bias[n + 1]; }
                if (MODE == 1 || MODE == 3) {
                    const float2 rv = *(const float2*)(res + m * 256 + n);
                    v0 = (v0 + rv.x) * keep;
                    v1 = (v1 + rv.y) * keep;
                }
                if (MODE == 2) { v0 = fmaxf(v0, 0.f); v1 = fmaxf(v1, 0.f); }
                if (MODE == 4) {
                    __half* dst = (n < 256) ? (g_Kh + m * 256 + n)
                                            : (g_Vh + m * 256 + (n - 256));
                    *(__half2*)dst = __floats2half2_rn(v0, v1);
                } else if (MODE == 0 || MODE == 2) {
                    *(__half2*)(CoutH + m * 256 + n) = __floats2half2_rn(v0, v1);
                } else {
                    *(float2*)(Cout + m * 256 + n) = make_float2(v0, v1);
                    if (MODE == 3)
                        *(__half2*)(CoutH + m * 256 + n) = __floats2half2_rn(v0, v1);
                }
            }
        }
    }
}

// ----------------------------------------------------------------------------
// Cluster-bucketed attention v2: 512 threads, 2 threads per query (32 dims
// each). Pair-local shfl mask — the two lanes of a pair share q/cluster, so
// they always converge; different pairs never participate in each other's shfl.
// ----------------------------------------------------------------------------
__global__ __launch_bounds__(512, 1) void attn_kernel(const int* __restrict__ seq) {
    extern __shared__ float sm[];
    float* Ks = sm;                    // [256][64]
    float* Vs = sm + Tn * DHn;
    __shared__ int sids[Tn];
    __shared__ int klist[Tn];
    __shared__ int cnt[Kcl], off[Kcl], cur[Kcl];

    const int b = blockIdx.x >> 2;     // Hn = 4
    const int h = blockIdx.x & 3;
    const int tid = threadIdx.x;

    const __half2* Kg = (const __half2*)g_Kh;
    const __half2* Vg = (const __half2*)g_Vh;
    for (int idx = tid; idx < Tn * 32; idx += 512) {
        int t = idx >> 5, d2 = idx & 31;
        int gi2 = ((b * Tn + t) * Cn + h * DHn) / 2 + d2;
        float2 kf = __half22float2(Kg[gi2]);
        float2 vf = __half22float2(Vg[gi2]);
        Ks[t * DHn + d2 * 2]     = kf.x;
        Ks[t * DHn + d2 * 2 + 1] = kf.y;
        Vs[t * DHn + d2 * 2]     = vf.x;
        Vs[t * DHn + d2 * 2 + 1] = vf.y;
    }
    if (tid < Tn) sids[tid] = g_ids[b * Tn + tid];
    if (tid < Kcl) cnt[tid] = 0;
    __syncthreads();
    if (tid < Tn) atomicAdd(&cnt[sids[tid]], 1);
    __syncthreads();
    if (tid == 0) {
        int acc = 0;
        for (int k = 0; k < Kcl; k++) { off[k] = acc; cur[k] = acc; acc += cnt[k]; }
    }
    __syncthreads();
    if (tid < Tn) {
        int c = sids[tid];
        int pos = atomicAdd(&cur[c], 1);
        klist[pos] = tid;
    }
    __syncthreads();

    const int lane = tid & 31;
    const unsigned pmask = 0x3u << (lane & ~1);   // pair-local shfl mask
    const int qpos = tid >> 1;
    const int half = tid & 1;
    const int q = klist[qpos];
    const int c = sids[q];
    const bool qvalid = (seq[b * Tn + q] != 0);

    float4 qv[8];
    {
        const __half2* qp = (const __half2*)(g_Qh + (b * Tn + q) * Cn + h * DHn + half * 32);
        #pragma unroll
        for (int j = 0; j < 8; j++) {
            float2 f0 = __half22float2(qp[j * 2]);
            float2 f1 = __half22float2(qp[j * 2 + 1]);
            qv[j] = make_float4(f0.x, f0.y, f1.x, f1.y);
        }
    }

    float m = -1e30f, ssum = 0.f;
    float4 accv[8];
    #pragma unroll
    for (int j = 0; j < 8; j++) accv[j] = make_float4(0.f, 0.f, 0.f, 0.f);

    if (qvalid) {
        const int cbeg = off[c];
        const int cend = cbeg + cnt[c];
        for (int j = cbeg; j < cend; j++) {
            int k = klist[j];
            const float4* kp = (const float4*)&Ks[k * DHn + half * 32];
            float d0 = 0.f, d1 = 0.f, d2 = 0.f, d3 = 0.f;
            #pragma unroll
            for (int jj = 0; jj < 8; jj++) {
                float4 kvv = kp[jj];
                d0 += qv[jj].x * kvv.x;
                d1 += qv[jj].y * kvv.y;
                d2 += qv[jj].z * kvv.z;
                d3 += qv[jj].w * kvv.w;
            }
            float dot = (d0 + d1) + (d2 + d3);
            dot += __shfl_xor_sync(pmask, dot, 1);   // pair reduce
            float s = dot * 0.125f;
            float nm = fmaxf(m, s);
            float cs = __expf(m - nm);
            float p  = __expf(s - nm);
            ssum = ssum * cs + p;
            const float4* vp = (const float4*)&Vs[k * DHn + half * 32];
            #pragma unroll
            for (int jj = 0; jj < 8; jj++) {
                float4 vv = vp[jj];
                accv[jj].x = accv[jj].x * cs + p * vv.x;
                accv[jj].y = accv[jj].y * cs + p * vv.y;
                accv[jj].z = accv[jj].z * cs + p * vv.z;
                accv[jj].w = accv[jj].w * cs + p * vv.w;
            }
            m = nm;
        }
    }

    float inv = qvalid ? (1.0f / ssum) : 0.0f;
    __half2* op = (__half2*)(g_attnh + (b * Tn + q) * Cn + h * DHn + half * 32);
    #pragma unroll
    for (int j = 0; j < 8; j++) {
        op[j * 2 + 0] = __floats2half2_rn(accv[j].x * inv, accv[j].y * inv);
        op[j * 2 + 1] = __floats2half2_rn(accv[j].z * inv, accv[j].w * inv);
    }
}

// ----------------------------------------------------------------------------
// Fused final LayerNorm + logits
// ----------------------------------------------------------------------------
__global__ __launch_bounds__(256) void lnlogits_kernel(const int* __restrict__ uid,
                                                       const int* __restrict__ pos_seqs,
                                                       const int* __restrict__ neg_seqs,
                                                       const float* __restrict__ item_emb,
                                                       const float* __restrict__ user_emb,
                                                       const float* __restrict__ lnfg,
                                                       const float* __restrict__ lnfb,
                                                       float* __restrict__ out) {
    int lane = threadIdx.x & 31, warp = threadIdx.x >> 5;
    int i = blockIdx.x * 8 + warp;
    int b = i >> 8;
    const float* r = g_x + i * Cn;
    float v[8];
    #pragma unroll
    for (int j = 0; j < 8; j++) v[j] = r[lane + 32 * j];
    float s = 0.f;
    #pragma unroll
    for (int j = 0; j < 8; j++) s += v[j];
    s = warp_sum(s);
    float mu = s * (1.0f / 256.0f);
    float q = 0.f;
    #pragma unroll
    for (int j = 0; j < 8; j++) { float d = v[j] - mu; q += d * d; }
    q = warp_sum(q);
    float rinv = rsqrtf(q * (1.0f / 256.0f) + 1e-8f);

    const float* pe = item_emb + pos_seqs[i] * ITEM_H;
    const float* ne = item_emb + neg_seqs[i] * ITEM_H;
    const float* ul = user_emb + uid[b] * USER_H;

    float sp = 0.f, sn = 0.f;
    #pragma unroll
    for (int j = 0; j < 8; j++) {
        int c = lane + 32 * j;
        float o = lnfg[c] * (v[j] - mu) * rinv + lnfb[c];
        if (c < ITEM_H) {
            sp += o * pe[c];
            sn += o * ne[c];
        } else {
            float u = ul[c - ITEM_H];
            sp += o * u;
            sn += o * u;
        }
    }
    sp = warp_sum(sp);
    sn = warp_sum(sn);
    if (lane == 0) {
        out[i]        = sp;
        out[NTOK + i] = sn;
    }
}

// ----------------------------------------------------------------------------
// Launch
// ----------------------------------------------------------------------------
extern "C" void kernel_launch(void* const* d_in, const int* in_sizes, int n_in,
                              void* d_out, int out_size) {
    const int*   uid      = (const int*)d_in[0];
    const int*   seq      = (const int*)d_in[1];
    const int*   pos_seqs = (const int*)d_in[2];
    const int*   neg_seqs = (const int*)d_in[3];
    const float* item_emb = (const float*)d_in[4];
    const float* user_emb = (const float*)d_in[5];
    const float* pos_emb  = (const float*)d_in[6];
    const float* Wq = (const float*)d_in[7];
    const float* Wk = (const float*)d_in[8];
    const float* Wv = (const float*)d_in[9];
    const float* Wo = (const float*)d_in[10];
    const float* ln1g = (const float*)d_in[11];
    const float* ln1b = (const float*)d_in[12];
    const float* ln2g = (const float*)d_in[13];
    const float* ln2b = (const float*)d_in[14];
    const float* W1 = (const float*)d_in[15];
    const float* b1 = (const float*)d_in[16];
    const float* W2 = (const float*)d_in[17];
    const float* b2 = (const float*)d_in[18];
    const float* lnfg = (const float*)d_in[19];
    const float* lnfb = (const float*)d_in[20];
    float* out = (float*)d_out;

    float *px, *pqin;
    __half *pxh, *pqinh, *pattnh, *ph1h, *pwh, *pwkv, *pQh;
    cudaGetSymbolAddress((void**)&px,     g_x);
    cudaGetSymbolAddress((void**)&pqin,   g_qin);
    cudaGetSymbolAddress((void**)&pxh,    g_xh);
    cudaGetSymbolAddress((void**)&pqinh,  g_qinh);
    cudaGetSymbolAddress((void**)&pattnh, g_attnh);
    cudaGetSymbolAddress((void**)&ph1h,   g_h1h);
    cudaGetSymbolAddress((void**)&pwh,    g_Wh);
    cudaGetSymbolAddress((void**)&pwkv,   g_Wkvh);
    cudaGetSymbolAddress((void**)&pQh,    g_Qh);

    const int WSZ = Cn * Cn;
    const int ASZ = Ln * WSZ;

    const int attn_smem = 2 * Tn * DHn * (int)sizeof(float);  // 128 KB
    cudaFuncSetAttribute(attn_kernel, cudaFuncAttributeMaxDynamicSharedMemorySize, attn_smem);
    cudaFuncSetAttribute(hgemm_kernel<0, 256>, cudaFuncAttributeMaxDynamicSharedMemorySize, GEMM_SMEM);
    cudaFuncSetAttribute(hgemm_kernel<1, 256>, cudaFuncAttributeMaxDynamicSharedMemorySize, GEMM_SMEM);
    cudaFuncSetAttribute(hgemm_kernel<2, 256>, cudaFuncAttributeMaxDynamicSharedMemorySize, GEMM_SMEM);
    cudaFuncSetAttribute(hgemm_kernel<3, 256>, cudaFuncAttributeMaxDynamicSharedMemorySize, GEMM_SMEM);
    cudaFuncSetAttribute(hgemm_kernel<4, 512>, cudaFuncAttributeMaxDynamicSharedMemorySize, GEMM_SMEM);

    const dim3 ggrid(Cn / 128, NTOK / 128);       // 2 x 1024
    const dim3 kvgrid(2 * Cn / 128, NTOK / 128);  // 4 x 1024

    const int conv_total = 4 * ASZ + Ln * Cn * 2 * Cn;   // 786432

    embed_kernel<<<NC / 256, 256>>>(uid, seq, item_emb, user_emb, pos_emb);       // 0
    kmeans_kernel<<<Bn, 256>>>(seq);                                              // 1
    convall_kernel<<<conv_total / 256, 256>>>(Wq, Wo, W1, W2, Wk, Wv);            // 2

    for (int l = 0; l < Ln; l++) {
        const __half* whq  = pwh + 0 * ASZ + l * WSZ;
        const __half* who  = pwh + 1 * ASZ + l * WSZ;
        const __half* wh1  = pwh + 2 * ASZ + l * WSZ;
        const __half* wh2  = pwh + 3 * ASZ + l * WSZ;
        const __half* whkv = pwkv + l * Cn * 2 * Cn;

        // fused K+V projection (index 3 on l=0: profiled slot)
        hgemm_kernel<4, 512><<<kvgrid, 256, GEMM_SMEM>>>(pxh, whkv, nullptr, nullptr, nullptr, nullptr, nullptr);
        // q_in = LN1(x): fp32 (residual) + fp16
        ln_kernel<true><<<NTOK / 8, 256>>>(px, pqin, pqinh, ln1g + l * Cn, ln1b + l * Cn);
        hgemm_kernel<0, 256><<<ggrid, 256, GEMM_SMEM>>>(pqinh, whq, nullptr, pQh, nullptr, nullptr, nullptr);
        // bucketed attention (512 threads)
        attn_kernel<<<Bn * Hn, 512, attn_smem>>>(seq);
        // x = (q_in + attn @ Wo) * keep
        hgemm_kernel<1, 256><<<ggrid, 256, GEMM_SMEM>>>(pattnh, who, px, nullptr, pqin, nullptr, seq);
        // f = LN2(x): fp16 only
        ln_kernel<false><<<NTOK / 8, 256>>>(px, nullptr, pqinh, ln2g + l * Cn, ln2b + l * Cn);
        // h1 = relu(f @ W1 + b1)
        hgemm_kernel<2, 256><<<ggrid, 256, GEMM_SMEM>>>(pqinh, wh1, nullptr, ph1h, nullptr, b1 + l * Cn, nullptr);
        // x = (x + h1 @ W2 + b2) * keep
        hgemm_kernel<3, 256><<<ggrid, 256, GEMM_SMEM>>>(ph1h, wh2, px, pxh, px, b2 + l * Cn, seq);
    }

    // fused final LN + logits
    lnlogits_kernel<<<NTOK / 8, 256>>>(uid, pos_seqs, neg_seqs, item_emb, user_emb,
                                       lnfg, lnfb, out);
}